// round 7
// baseline (speedup 1.0000x reference)
#include <cuda_runtime.h>
#include <math.h>

// Shapes fixed: B=8192, D=128, R=64, C=64.
// exp(logit) underflows to exact 0 for all but ~4000 of 524288 (b,r) pairs.
// kA: zero/coefs. kC: firing strengths (quadratic form, packed f32x2 FMA)
// + BN partial sums from already-loaded registers + per-rule compaction.
// kD: BN finalize (redundant per block, L2-broadcast) + gathered per-rule GEMV.

typedef unsigned long long u64;

// ---------------- device scratch ----------------
__device__ float  g_psum[128 * 128];     // BN partial sums  [d][blk]
__device__ float  g_psq [128 * 128];     // BN partial sumsq [d][blk]
__device__ float4 g_coef[4096];          // [d][lane] = (u_l, m_l, u_{l+32}, m_{l+32})
__device__ float  g_csum[64];            // per-rule sum_d c^2 u
__device__ int    g_count[64];           // nonzero rows per rule
__device__ int    g_rows [64 * 8192];
__device__ float  g_fvals[64 * 8192];

__device__ __forceinline__ void ffma2(u64& d, u64 a, u64 b) {
    asm("fma.rn.f32x2 %0, %1, %2, %0;" : "+l"(d) : "l"(a), "l"(b));
}
__device__ __forceinline__ u64 pack2(float lo, float hi) {
    u64 r; asm("mov.b64 %0, {%1, %2};" : "=l"(r) : "f"(lo), "f"(hi)); return r;
}
__device__ __forceinline__ float2 unpack2(u64 v) {
    float2 r; asm("mov.b64 {%0, %1}, %2;" : "=f"(r.x), "=f"(r.y) : "l"(v)); return r;
}

// ---------------- kA: zero out + coef pack + csum + counters ----------------
// grid 64, block 256
__global__ void kA_prep(const float* __restrict__ centers,
                        const float* __restrict__ sigmas,
                        float4* __restrict__ out4) {
    __shared__ float ps[256];
    int blk = blockIdx.x, tid = threadIdx.x;

    float4 z4 = make_float4(0.f, 0.f, 0.f, 0.f);
    #pragma unroll
    for (int k = 0; k < 8; ++k)
        out4[blk * 2048 + k * 256 + tid] = z4;       // 131072 float4 total

    if (blk == 0 && tid < 64) g_count[tid] = 0;

    // pack quadratic coefficients: 64 float4 per block
    if (tid < 64) {
        int f = blk * 64 + tid;                      // f = d*32 + ln
        int d = f >> 5, ln = f & 31;
        float c0 = centers[d * 64 + ln],      s0 = sigmas[d * 64 + ln];
        float c1 = centers[d * 64 + ln + 32], s1 = sigmas[d * 64 + ln + 32];
        float u0 = 1.0f / (2.0f * s0 * s0);
        float u1 = 1.0f / (2.0f * s1 * s1);
        g_coef[f] = make_float4(u0, -2.0f * c0 * u0, u1, -2.0f * c1 * u1);
    }

    if (blk == 0) {
        // per-rule csum = sum_d c^2 u (r = tid&63, quarter q = tid>>6)
        int r = tid & 63, q = tid >> 6;
        float cs = 0.f;
        #pragma unroll 8
        for (int dd = 0; dd < 32; ++dd) {
            int d = q * 32 + dd;
            float c = centers[d * 64 + r], sg = sigmas[d * 64 + r];
            cs = fmaf(c * c, 1.0f / (2.0f * sg * sg), cs);
        }
        ps[tid] = cs;
        __syncthreads();
        if (tid < 64)
            g_csum[tid] = (ps[tid] + ps[tid + 64]) + (ps[tid + 128] + ps[tid + 192]);
    }
}

// ---------------- kC: firing strengths + compaction + BN partials ----------------
// grid 128, block 512 (16 warps). Each warp: 4 consecutive rows, all 64 rules
// (lane covers rules lane, lane+32 via packed f32x2 accumulators).
__global__ void __launch_bounds__(512)
kC_frs(const float* __restrict__ x,
       const float* __restrict__ rule_masks) {
    extern __shared__ float4 cs4[];      // coef copy, 4096 float4 = 64KB
    __shared__ float bnS[16 * 128], bnQ[16 * 128];
    int tid = threadIdx.x, blk = blockIdx.x;
    int lane = tid & 31, wid = tid >> 5;

    #pragma unroll
    for (int k = 0; k < 8; ++k) cs4[k * 512 + tid] = g_coef[k * 512 + tid];
    __syncthreads();

    float m0 = rule_masks[lane];
    float m1 = rule_masks[lane + 32];
    float cc0 = g_csum[lane];
    float cc1 = g_csum[lane + 32];

    int b0 = (blk * 16 + wid) * 4;       // 4 consecutive rows per warp
    float xq[4][4];
    #pragma unroll
    for (int r = 0; r < 4; ++r)
        #pragma unroll
        for (int j = 0; j < 4; ++j)
            xq[r][j] = x[(size_t)(b0 + r) * 128 + j * 32 + lane];

    u64 acc[4][2];
    #pragma unroll
    for (int r = 0; r < 4; ++r) { acc[r][0] = 0ull; acc[r][1] = 0ull; }

    const ulonglong2* cs2 = (const ulonglong2*)cs4;
    #pragma unroll
    for (int j = 0; j < 4; ++j) {
        #pragma unroll 8
        for (int t = 0; t < 32; ++t) {
            ulonglong2 cf = cs2[(j * 32 + t) * 32 + lane];  // (u0,m0),(u1,m1)
            #pragma unroll
            for (int r = 0; r < 4; ++r) {
                float xd = __shfl_sync(0xffffffffu, xq[r][j], t);
                u64 xp = pack2(xd * xd, xd);
                ffma2(acc[r][0], xp, cf.x);
                ffma2(acc[r][1], xp, cf.y);
            }
        }
    }

    // BN partial sums from registers (covers this warp's 4 rows)
    #pragma unroll
    for (int j = 0; j < 4; ++j) {
        float s = (xq[0][j] + xq[1][j]) + (xq[2][j] + xq[3][j]);
        float q = (xq[0][j] * xq[0][j] + xq[1][j] * xq[1][j])
                + (xq[2][j] * xq[2][j] + xq[3][j] * xq[3][j]);
        bnS[wid * 128 + j * 32 + lane] = s;
        bnQ[wid * 128 + j * 32 + lane] = q;
    }

    // firing strengths + per-rule compaction
    #pragma unroll
    for (int r = 0; r < 4; ++r) {
        int b = b0 + r;
        float2 a0 = unpack2(acc[r][0]);
        float2 a1 = unpack2(acc[r][1]);
        float raw0 = __expf(-(a0.x + a0.y + cc0)) * m0;
        float raw1 = __expf(-(a1.x + a1.y + cc1)) * m1;
        float s = raw0 + raw1;
        #pragma unroll
        for (int off = 16; off; off >>= 1)
            s += __shfl_xor_sync(0xffffffffu, s, off);
        float den = s + 1e-10f;
        float f0 = raw0 / den, f1 = raw1 / den;
        if (f0 > 0.f) { int q = atomicAdd(&g_count[lane], 1);
                        g_rows[lane * 8192 + q] = b; g_fvals[lane * 8192 + q] = f0; }
        if (f1 > 0.f) { int q = atomicAdd(&g_count[lane + 32], 1);
                        g_rows[(lane + 32) * 8192 + q] = b; g_fvals[(lane + 32) * 8192 + q] = f1; }
    }

    __syncthreads();
    if (tid < 128) {
        float ss = 0.f, qq = 0.f;
        #pragma unroll
        for (int w = 0; w < 16; ++w) {
            ss += bnS[w * 128 + tid];
            qq += bnQ[w * 128 + tid];
        }
        g_psum[tid * 128 + blk] = ss;
        g_psq [tid * 128 + blk] = qq;
    }
}

// ---------------- kD: BN finalize + per-rule gathered GEMV ----------------
// grid (2, 64), block 256. scsh computed redundantly per block (L2-broadcast),
// W[r] staged in smem, lane covers 2 output cols.
__global__ void kD_out(const float* __restrict__ x,
                       const float* __restrict__ weights,
                       const float* __restrict__ biases,
                       const float* __restrict__ gamma,
                       const float* __restrict__ beta,
                       float* __restrict__ out) {
    int r = blockIdx.y;
    __shared__ float4 Ws4[2048];         // W[r]: 32KB
    __shared__ float2 scsh[128];
    __shared__ float  bias_s[64];
    int tid = threadIdx.x;

    const float4* Wg = (const float4*)(weights + (size_t)r * 8192);
    #pragma unroll
    for (int k = 0; k < 8; ++k) Ws4[k * 256 + tid] = Wg[k * 256 + tid];
    if (tid < 64) bias_s[tid] = biases[r * 64 + tid];

    // BN finalize: 2 threads per d, 64 partials each
    {
        int d = tid >> 1, half = tid & 1;
        const float* pp = g_psum + d * 128 + half * 64;
        const float* pq = g_psq  + d * 128 + half * 64;
        float ss = 0.f, qq = 0.f;
        #pragma unroll 16
        for (int k = 0; k < 64; ++k) { ss += pp[k]; qq += pq[k]; }
        ss += __shfl_xor_sync(0xffffffffu, ss, 1);
        qq += __shfl_xor_sync(0xffffffffu, qq, 1);
        if (half == 0) {
            float mean = ss * (1.0f / 8192.0f);
            float var  = fmaxf(qq * (1.0f / 8192.0f) - mean * mean, 0.0f);
            float sc = gamma[d] / sqrtf(var + 1e-5f);
            scsh[d] = make_float2(sc, beta[d] - mean * sc);
        }
    }
    __syncthreads();

    int cnt = g_count[r];
    const float* Ws = (const float*)Ws4;
    int lane = tid & 31, wid = tid >> 5;
    int c = lane * 2;

    for (int i = blockIdx.x * 8 + wid; i < cnt; i += 16) {
        int b   = g_rows [r * 8192 + i];
        float f = g_fvals[r * 8192 + i];
        float xnv[4];
        #pragma unroll
        for (int j = 0; j < 4; ++j) {
            float2 ss = scsh[j * 32 + lane];
            xnv[j] = x[(size_t)b * 128 + j * 32 + lane] * ss.x + ss.y;
        }
        float a0 = 0.f, a1 = 0.f;
        #pragma unroll
        for (int j = 0; j < 4; ++j) {
            float xv = xnv[j];
            #pragma unroll 8
            for (int t = 0; t < 32; ++t) {
                float xk = __shfl_sync(0xffffffffu, xv, t);
                float2 w = *(const float2*)(Ws + (j * 32 + t) * 64 + c);
                a0 = fmaf(xk, w.x, a0);
                a1 = fmaf(xk, w.y, a1);
            }
        }
        atomicAdd(out + (size_t)b * 64 + c,     f * (a0 + bias_s[c]));
        atomicAdd(out + (size_t)b * 64 + c + 1, f * (a1 + bias_s[c + 1]));
    }
}

// ---------------- launch ----------------
extern "C" void kernel_launch(void* const* d_in, const int* in_sizes, int n_in,
                              void* d_out, int out_size) {
    const float* x       = (const float*)d_in[0];
    const float* centers = (const float*)d_in[1];
    const float* sigmas  = (const float*)d_in[2];
    const float* weights = (const float*)d_in[3];
    const float* biases  = (const float*)d_in[4];
    const float* gamma   = (const float*)d_in[5];
    const float* beta    = (const float*)d_in[6];
    const float* masks   = (const float*)d_in[7];
    float* out = (float*)d_out;

    cudaFuncSetAttribute(kC_frs, cudaFuncAttributeMaxDynamicSharedMemorySize, 65536);

    kA_prep<<<64, 256>>>(centers, sigmas, (float4*)out);
    kC_frs<<<128, 512, 65536>>>(x, masks);
    dim3 gD(2, 64);
    kD_out<<<gD, 256>>>(x, weights, biases, gamma, beta, out);
}